// round 7
// baseline (speedup 1.0000x reference)
#include <cuda_runtime.h>
#include <cuda_bf16.h>

// Problem constants (fixed by the reference's setup_inputs)
#define N_NODES  100000
#define E_EDGES  1600000
#define FLOW_ITERS 10

// Persistent-kernel geometry: must be co-resident for the software grid barrier.
#define GRID 888                               // 6 blocks/SM x 148 SMs
#define TPB  256
#define TTOT (GRID * TPB)                      // 227,328 threads
#define EPT_FULL (E_EDGES / TTOT)              // 7 full strides
#define EPT (EPT_FULL + 1)                     // 8 (last stride partial)
#define E_TAIL (E_EDGES - EPT_FULL * TTOT)     // 8,704 edges in last stride

// Scratch (__device__ globals; no cudaMalloc allowed)
__device__ int      g_deg[N_NODES];
__device__ float    g_acc[3][N_NODES];         // acc = inflow - d0 (init -d0)
__device__ unsigned g_count;                   // barrier arrival counter
__device__ unsigned g_gen;                     // barrier generation

// Software grid barrier. The gpu-scope __threadfence() emits CCTL.IVALL on
// sm_103a, invalidating this SM's L1D — which makes plain (L1-cached) loads
// of atomics-written data coherent across barrier phases.
__device__ __forceinline__ void gbar() {
    __syncthreads();
    if (threadIdx.x == 0) {
        unsigned old = *(volatile unsigned*)&g_gen;   // read BEFORE arriving
        __threadfence();
        if (atomicAdd(&g_count, 1u) == GRID - 1) {
            g_count = 0;
            __threadfence();
            atomicAdd(&g_gen, 1u);                    // release
        } else {
            while (*(volatile unsigned*)&g_gen == old) { __nanosleep(32); }
        }
        __threadfence();                              // acquire + L1 IVALL
    }
    __syncthreads();
}

// ---------------------------------------------------------------------------
// Persistent fused kernel. Edge indices + per-edge fw live in registers for
// all 10 iterations. Per edge per iteration: ONE 4-byte gather (L1-cached,
// coherent via barrier IVALL) + ONE REDG scatter. acc buffers hold
// (inflow - d0), so the relu operand needs no extra fields. 3-buffer
// rotation -> one grid barrier per iteration.
// ---------------------------------------------------------------------------
__global__ void __launch_bounds__(TPB, 6)
k_persist(const int* __restrict__ src_g, const int* __restrict__ dst_g,
          const float* __restrict__ d0, float* __restrict__ out)
{
    const int tid = blockIdx.x * TPB + threadIdx.x;
    float* __restrict__ flow_out = out + 1;
    float* __restrict__ fw_out   = out + 1 + E_EDGES;

    const bool tail_ok = (tid < E_TAIL);

    // Load edge indices into registers (coalesced strided layout).
    int esrc[EPT], edst[EPT];
    float efw[EPT];
#pragma unroll
    for (int k = 0; k < EPT_FULL; k++) {
        esrc[k] = __ldg(src_g + tid + k * TTOT);
        edst[k] = __ldg(dst_g + tid + k * TTOT);
    }
    esrc[EPT_FULL] = tail_ok ? __ldg(src_g + tid + EPT_FULL * TTOT) : 0;
    edst[EPT_FULL] = tail_ok ? __ldg(dst_g + tid + EPT_FULL * TTOT) : 0;

    // Phase 1: zero deg, init all 3 acc buffers to -d0, zero cost.
    if (tid < N_NODES) {
        g_deg[tid] = 0;
        float nd0 = -__ldg(&d0[tid]);
        __stcg(&g_acc[0][tid], nd0);
        __stcg(&g_acc[1][tid], nd0);
        __stcg(&g_acc[2][tid], nd0);
    }
    if (tid == 0) out[0] = 0.0f;
    gbar();

    // Phase 2: out-degree histogram of src.
#pragma unroll
    for (int k = 0; k < EPT_FULL; k++) atomicAdd(&g_deg[esrc[k]], 1);
    if (tail_ok) atomicAdd(&g_deg[esrc[EPT_FULL]], 1);
    gbar();

    // Iter 0 (peeled): fw[e] = 1/(deg[src]+1e-9) (bitwise identical to the
    // reference segment softmax: all scores per segment equal -> exp==1,
    // den==deg exactly). flow_0 = fw. Scatter fw into buf0, emit fw output.
    {
        const int* dr = g_deg;          // L1-cached gather (post-barrier safe)
#pragma unroll
        for (int k = 0; k < EPT; k++) {
            bool ok = (k < EPT_FULL) || tail_ok;
            float f = 0.0f;
            if (ok) {
                float den = (float)dr[esrc[k]] + 1e-9f;
                f = 1.0f / den;
                fw_out[tid + k * TTOT] = f;
                atomicAdd(&g_acc[0][edst[k]], f);
            }
            efw[k] = f;
        }
        gbar();
    }

    // Iters 1..9: read buf[(it-1)%3], write buf[it%3], reset buf[(it+1)%3]
    // to -d0 (it was last read two barriers ago -> race-free).
    for (int it = 1; it < FLOW_ITERS; ++it) {
        const float* nr = g_acc[(it - 1) % 3];   // L1-cached reads (immutable
        float* nw = g_acc[it % 3];               //   this phase; IVALL at bar)
        float* nz = g_acc[(it + 1) % 3];

#pragma unroll
        for (int k = 0; k < EPT_FULL; k++) {
            float v = efw[k] * fmaxf(nr[esrc[k]], 0.0f);
            atomicAdd(&nw[edst[k]], v);
        }
        if (tail_ok) {
            float v = efw[EPT_FULL] * fmaxf(nr[esrc[EPT_FULL]], 0.0f);
            atomicAdd(&nw[edst[EPT_FULL]], v);
        }
        if (tid < N_NODES && it + 1 < FLOW_ITERS)
            __stcg(&nz[tid], -__ldg(&d0[tid]));
        gbar();
    }

    // Epilogue: final accumulator is buf[(FLOW_ITERS-1)%3] = buf0.
    // flow = fw * relu(acc[src]); accumulate sum(flow^2).
    const float* nf = g_acc[(FLOW_ITERS - 1) % 3];
    float acc = 0.0f;
#pragma unroll
    for (int k = 0; k < EPT_FULL; k++) {
        float fl = efw[k] * fmaxf(nf[esrc[k]], 0.0f);
        flow_out[tid + k * TTOT] = fl;
        acc += fl * fl;
    }
    if (tail_ok) {
        float fl = efw[EPT_FULL] * fmaxf(nf[esrc[EPT_FULL]], 0.0f);
        flow_out[tid + EPT_FULL * TTOT] = fl;
        acc += fl * fl;
    }

    // Block-reduce cost, one atomicAdd per block.
    __shared__ float warp_part[TPB / 32];
#pragma unroll
    for (int o = 16; o > 0; o >>= 1)
        acc += __shfl_down_sync(0xFFFFFFFF, acc, o);
    int lane = threadIdx.x & 31, wid = threadIdx.x >> 5;
    if (lane == 0) warp_part[wid] = acc;
    __syncthreads();
    if (wid == 0) {
        acc = (lane < TPB / 32) ? warp_part[lane] : 0.0f;
#pragma unroll
        for (int o = 16; o > 0; o >>= 1)
            acc += __shfl_down_sync(0xFFFFFFFF, acc, o);
        if (lane == 0) atomicAdd(out, acc);
    }
}

// ======================= Fallback path (proven R3 kernels) ==================
__device__ float g_inflow2[2][N_NODES];

__global__ void k_zero(float* __restrict__ out0) {
    int i = blockIdx.x * blockDim.x + threadIdx.x;
    if (i < N_NODES) {
        g_deg[i] = 0;
        g_inflow2[0][i] = 0.0f;
        g_inflow2[1][i] = 0.0f;
    }
    if (i == 0) *out0 = 0.0f;
}

__global__ void k_count(const int* __restrict__ src, int E) {
    int i = blockIdx.x * blockDim.x + threadIdx.x;
    if (i < E) atomicAdd(&g_deg[__ldg(&src[i])], 1);
}

__global__ void k_init(const int* __restrict__ src,
                       float* __restrict__ flow,
                       float* __restrict__ fw, int E) {
    int i = blockIdx.x * blockDim.x + threadIdx.x;
    if (i < E) {
        float den = (float)g_deg[__ldg(&src[i])] + 1e-9f;
        float f = 1.0f / den;
        fw[i]   = f;
        flow[i] = f;
    }
}

__global__ void k_scatter(const int* __restrict__ dst,
                          const float* __restrict__ flow, int E, int buf) {
    int i2 = blockIdx.x * blockDim.x + threadIdx.x;
    int i  = i2 * 2;
    if (i + 1 < E) {
        int2  d  = *(const int2*)(dst + i);
        float f0 = __ldg(&flow[i]);
        float f1 = __ldg(&flow[i + 1]);
        atomicAdd(&g_inflow2[buf][d.x], f0);
        atomicAdd(&g_inflow2[buf][d.y], f1);
    } else if (i < E) {
        atomicAdd(&g_inflow2[buf][__ldg(&dst[i])], __ldg(&flow[i]));
    }
}

__global__ void k_apply(const int* __restrict__ src,
                        const float* __restrict__ fw,
                        const float* __restrict__ d0,
                        float* __restrict__ flow, int E, int buf) {
    int i2 = blockIdx.x * blockDim.x + threadIdx.x;
    int i  = i2 * 2;
    const float* __restrict__ infl = g_inflow2[buf];
    if (i + 1 < E) {
        int2  s  = *(const int2*)(src + i);
        float w0 = __ldg(&fw[i]);
        float w1 = __ldg(&fw[i + 1]);
        float a0 = fmaxf(__ldg(&infl[s.x]) - __ldg(&d0[s.x]), 0.0f);
        float a1 = fmaxf(__ldg(&infl[s.y]) - __ldg(&d0[s.y]), 0.0f);
        flow[i]     = w0 * a0;
        flow[i + 1] = w1 * a1;
    } else if (i < E) {
        int s = __ldg(&src[i]);
        float a = fmaxf(__ldg(&infl[s]) - __ldg(&d0[s]), 0.0f);
        flow[i] = __ldg(&fw[i]) * a;
    }
    if (i2 < N_NODES) g_inflow2[buf ^ 1][i2] = 0.0f;
}

__global__ void k_cost(const float* __restrict__ flow, float* __restrict__ out0, int E) {
    __shared__ float warp_part[32];
    float acc = 0.0f;
    for (int i = blockIdx.x * blockDim.x + threadIdx.x; i < E;
         i += gridDim.x * blockDim.x) {
        float v = __ldg(&flow[i]);
        acc += v * v;
    }
    #pragma unroll
    for (int o = 16; o > 0; o >>= 1)
        acc += __shfl_down_sync(0xFFFFFFFF, acc, o);
    int lane = threadIdx.x & 31;
    int wid  = threadIdx.x >> 5;
    if (lane == 0) warp_part[wid] = acc;
    __syncthreads();
    if (wid == 0) {
        int nw = (blockDim.x + 31) >> 5;
        acc = (lane < nw) ? warp_part[lane] : 0.0f;
        #pragma unroll
        for (int o = 16; o > 0; o >>= 1)
            acc += __shfl_down_sync(0xFFFFFFFF, acc, o);
        if (lane == 0) atomicAdd(out0, acc);
    }
}

// ---------------------------------------------------------------------------
// Launch. Inputs: demands, node_embeddings, edge_src, edge_dst, [weights...].
// Output layout: [flow_cost(1), flow(E), fw(E)]. The GNN is provably dead
// code w.r.t. the outputs (uniform per-segment softmax scores).
// ---------------------------------------------------------------------------
extern "C" void kernel_launch(void* const* d_in, const int* in_sizes, int n_in,
                              void* d_out, int out_size) {
    const float* demands = (const float*)d_in[0];   // N x 1
    const int*   src     = (const int*)  d_in[2];   // E
    const int*   dst     = (const int*)  d_in[3];   // E
    const int E = in_sizes[2];
    const int Nn = in_sizes[0];

    float* out  = (float*)d_out;
    float* flow = out + 1;       // E floats (only 4B aligned!)
    float* fw   = out + 1 + E;   // E floats (only 4B aligned!)

    // Can the persistent kernel's GRID blocks be fully co-resident?
    bool use_persist = (E == E_EDGES && Nn == N_NODES);
    if (use_persist) {
        int dev = 0, sms = 0, occ = 0;
        cudaGetDevice(&dev);
        cudaDeviceGetAttribute(&sms, cudaDevAttrMultiProcessorCount, dev);
        cudaOccupancyMaxActiveBlocksPerMultiprocessor(&occ, k_persist, TPB, 0);
        if ((long long)occ * sms < GRID) use_persist = false;
    }

    if (use_persist) {
        k_persist<<<GRID, TPB>>>(src, dst, demands, out);
        return;
    }

    // Fallback: proven multi-kernel path.
    const int T   = 256;
    const int BE  = (E + T - 1) / T;
    const int BE2 = (E / 2 + T) / T;
    const int BN  = (N_NODES + T - 1) / T;

    k_zero<<<BN, T>>>(out);
    k_count<<<BE, T>>>(src, E);
    k_init<<<BE, T>>>(src, flow, fw, E);
    for (int it = 0; it < FLOW_ITERS; ++it) {
        int buf = it & 1;
        k_scatter<<<BE2, T>>>(dst, flow, E, buf);
        k_apply<<<BE2, T>>>(src, fw, demands, flow, E, buf);
    }
    k_cost<<<1024, 256>>>(flow, out, E);
}

// round 8
// speedup vs baseline: 1.0767x; 1.0767x over previous
#include <cuda_runtime.h>
#include <cuda_bf16.h>

// Problem constants (fixed by the reference's setup_inputs)
#define N_NODES  100000
#define E_EDGES  1600000
#define FLOW_ITERS 10

// Persistent-kernel geometry: must be co-resident for the software grid barrier.
// 592 = 4 blocks/SM x 148 SMs (measured-best occupancy for this workload).
#define GRID 592
#define TPB  256
#define TTOT (GRID * TPB)                      // 151,552 threads
#define EPT_FULL (E_EDGES / TTOT)              // 10 full strides
#define EPT (EPT_FULL + 1)                     // 11 (last stride partial)
#define E_TAIL (E_EDGES - EPT_FULL * TTOT)     // 84,480 edges in last stride

// Scratch (__device__ globals; no cudaMalloc allowed)
__device__ int      g_deg[N_NODES];
__device__ float    g_acc[3][N_NODES];         // acc = inflow - d0 (init -d0)
__device__ unsigned g_count;                   // barrier arrival counter
__device__ unsigned g_gen;                     // barrier generation

// Software grid barrier. The gpu-scope __threadfence() emits CCTL.IVALL on
// sm_103a, invalidating this SM's L1D — which makes plain (L1-cached) loads
// of atomics-written data coherent across barrier phases (validated R7:
// rel_err 7e-7 with L1-cached gathers).
__device__ __forceinline__ void gbar() {
    __syncthreads();
    if (threadIdx.x == 0) {
        unsigned old = *(volatile unsigned*)&g_gen;   // read BEFORE arriving
        __threadfence();
        if (atomicAdd(&g_count, 1u) == GRID - 1) {
            g_count = 0;
            __threadfence();
            atomicAdd(&g_gen, 1u);                    // release
        } else {
            while (*(volatile unsigned*)&g_gen == old) { __nanosleep(32); }
        }
        __threadfence();                              // acquire + L1 IVALL
    }
    __syncthreads();
}

// ---------------------------------------------------------------------------
// Persistent fused kernel. Edge indices + per-edge fw live in registers for
// all 10 iterations. Per edge per iteration: ONE 4-byte gather (L1-cached,
// coherent via barrier IVALL) + at most ONE REDG scatter (skipped when the
// contribution is exactly zero). acc buffers hold (inflow - d0). 3-buffer
// rotation -> one grid barrier per iteration, 12 barriers total.
// ---------------------------------------------------------------------------
__global__ void __launch_bounds__(TPB, 4)
k_persist(const int* __restrict__ src_g, const int* __restrict__ dst_g,
          const float* __restrict__ d0, float* __restrict__ out)
{
    const int tid = blockIdx.x * TPB + threadIdx.x;
    float* __restrict__ flow_out = out + 1;
    float* __restrict__ fw_out   = out + 1 + E_EDGES;

    const bool tail_ok = (tid < E_TAIL);

    // Load edge indices into registers (coalesced strided layout).
    int esrc[EPT], edst[EPT];
    float efw[EPT];
#pragma unroll
    for (int k = 0; k < EPT_FULL; k++) {
        esrc[k] = __ldg(src_g + tid + k * TTOT);
        edst[k] = __ldg(dst_g + tid + k * TTOT);
    }
    esrc[EPT_FULL] = tail_ok ? __ldg(src_g + tid + EPT_FULL * TTOT) : 0;
    edst[EPT_FULL] = tail_ok ? __ldg(dst_g + tid + EPT_FULL * TTOT) : 0;

    // Phase 1: zero deg, init all 3 acc buffers to -d0, zero cost.
    if (tid < N_NODES) {
        g_deg[tid] = 0;
        float nd0 = -__ldg(&d0[tid]);
        __stcg(&g_acc[0][tid], nd0);
        __stcg(&g_acc[1][tid], nd0);
        __stcg(&g_acc[2][tid], nd0);
    }
    if (tid == 0) out[0] = 0.0f;
    gbar();

    // Phase 2: out-degree histogram of src.
#pragma unroll
    for (int k = 0; k < EPT_FULL; k++) atomicAdd(&g_deg[esrc[k]], 1);
    if (tail_ok) atomicAdd(&g_deg[esrc[EPT_FULL]], 1);
    gbar();

    // Iter 0 (peeled): fw[e] = 1/(deg[src]+1e-9) (bitwise identical to the
    // reference segment softmax: all scores per segment equal -> exp==1,
    // den==deg exactly). flow_0 = fw. Scatter fw into buf0, emit fw output.
    {
        const int* dr = g_deg;          // L1-cached gather (post-barrier safe)
#pragma unroll
        for (int k = 0; k < EPT; k++) {
            bool ok = (k < EPT_FULL) || tail_ok;
            float f = 0.0f;
            if (ok) {
                float den = (float)dr[esrc[k]] + 1e-9f;
                f = 1.0f / den;
                fw_out[tid + k * TTOT] = f;
                atomicAdd(&g_acc[0][edst[k]], f);
            }
            efw[k] = f;
        }
        gbar();
    }

    // Iters 1..9: read buf[(it-1)%3], write buf[it%3], reset buf[(it+1)%3]
    // to -d0 (it was last read two barriers ago -> race-free). Zero-valued
    // contributions are skipped: s + 0.0f == s for the running sums, and
    // the final relu/multiply erases any signed-zero difference.
    for (int it = 1; it < FLOW_ITERS; ++it) {
        const float* nr = g_acc[(it - 1) % 3];   // L1-cached reads (immutable
        float* nw = g_acc[it % 3];               //   this phase; IVALL at bar)
        float* nz = g_acc[(it + 1) % 3];

#pragma unroll
        for (int k = 0; k < EPT_FULL; k++) {
            float v = efw[k] * fmaxf(nr[esrc[k]], 0.0f);
            if (v != 0.0f) atomicAdd(&nw[edst[k]], v);
        }
        if (tail_ok) {
            float v = efw[EPT_FULL] * fmaxf(nr[esrc[EPT_FULL]], 0.0f);
            if (v != 0.0f) atomicAdd(&nw[edst[EPT_FULL]], v);
        }
        if (tid < N_NODES && it + 1 < FLOW_ITERS)
            __stcg(&nz[tid], -__ldg(&d0[tid]));
        gbar();
    }

    // Epilogue: final accumulator is buf[(FLOW_ITERS-1)%3] = buf0.
    // flow = fw * relu(acc[src]); accumulate sum(flow^2).
    const float* nf = g_acc[(FLOW_ITERS - 1) % 3];
    float acc = 0.0f;
#pragma unroll
    for (int k = 0; k < EPT_FULL; k++) {
        float fl = efw[k] * fmaxf(nf[esrc[k]], 0.0f);
        flow_out[tid + k * TTOT] = fl;
        acc += fl * fl;
    }
    if (tail_ok) {
        float fl = efw[EPT_FULL] * fmaxf(nf[esrc[EPT_FULL]], 0.0f);
        flow_out[tid + EPT_FULL * TTOT] = fl;
        acc += fl * fl;
    }

    // Block-reduce cost, one atomicAdd per block.
    __shared__ float warp_part[TPB / 32];
#pragma unroll
    for (int o = 16; o > 0; o >>= 1)
        acc += __shfl_down_sync(0xFFFFFFFF, acc, o);
    int lane = threadIdx.x & 31, wid = threadIdx.x >> 5;
    if (lane == 0) warp_part[wid] = acc;
    __syncthreads();
    if (wid == 0) {
        acc = (lane < TPB / 32) ? warp_part[lane] : 0.0f;
#pragma unroll
        for (int o = 16; o > 0; o >>= 1)
            acc += __shfl_down_sync(0xFFFFFFFF, acc, o);
        if (lane == 0) atomicAdd(out, acc);
    }
}

// ======================= Fallback path (proven R3 kernels) ==================
__device__ float g_inflow2[2][N_NODES];

__global__ void k_zero(float* __restrict__ out0) {
    int i = blockIdx.x * blockDim.x + threadIdx.x;
    if (i < N_NODES) {
        g_deg[i] = 0;
        g_inflow2[0][i] = 0.0f;
        g_inflow2[1][i] = 0.0f;
    }
    if (i == 0) *out0 = 0.0f;
}

__global__ void k_count(const int* __restrict__ src, int E) {
    int i = blockIdx.x * blockDim.x + threadIdx.x;
    if (i < E) atomicAdd(&g_deg[__ldg(&src[i])], 1);
}

__global__ void k_init(const int* __restrict__ src,
                       float* __restrict__ flow,
                       float* __restrict__ fw, int E) {
    int i = blockIdx.x * blockDim.x + threadIdx.x;
    if (i < E) {
        float den = (float)g_deg[__ldg(&src[i])] + 1e-9f;
        float f = 1.0f / den;
        fw[i]   = f;
        flow[i] = f;
    }
}

__global__ void k_scatter(const int* __restrict__ dst,
                          const float* __restrict__ flow, int E, int buf) {
    int i2 = blockIdx.x * blockDim.x + threadIdx.x;
    int i  = i2 * 2;
    if (i + 1 < E) {
        int2  d  = *(const int2*)(dst + i);
        float f0 = __ldg(&flow[i]);
        float f1 = __ldg(&flow[i + 1]);
        atomicAdd(&g_inflow2[buf][d.x], f0);
        atomicAdd(&g_inflow2[buf][d.y], f1);
    } else if (i < E) {
        atomicAdd(&g_inflow2[buf][__ldg(&dst[i])], __ldg(&flow[i]));
    }
}

__global__ void k_apply(const int* __restrict__ src,
                        const float* __restrict__ fw,
                        const float* __restrict__ d0,
                        float* __restrict__ flow, int E, int buf) {
    int i2 = blockIdx.x * blockDim.x + threadIdx.x;
    int i  = i2 * 2;
    const float* __restrict__ infl = g_inflow2[buf];
    if (i + 1 < E) {
        int2  s  = *(const int2*)(src + i);
        float w0 = __ldg(&fw[i]);
        float w1 = __ldg(&fw[i + 1]);
        float a0 = fmaxf(__ldg(&infl[s.x]) - __ldg(&d0[s.x]), 0.0f);
        float a1 = fmaxf(__ldg(&infl[s.y]) - __ldg(&d0[s.y]), 0.0f);
        flow[i]     = w0 * a0;
        flow[i + 1] = w1 * a1;
    } else if (i < E) {
        int s = __ldg(&src[i]);
        float a = fmaxf(__ldg(&infl[s]) - __ldg(&d0[s]), 0.0f);
        flow[i] = __ldg(&fw[i]) * a;
    }
    if (i2 < N_NODES) g_inflow2[buf ^ 1][i2] = 0.0f;
}

__global__ void k_cost(const float* __restrict__ flow, float* __restrict__ out0, int E) {
    __shared__ float warp_part[32];
    float acc = 0.0f;
    for (int i = blockIdx.x * blockDim.x + threadIdx.x; i < E;
         i += gridDim.x * blockDim.x) {
        float v = __ldg(&flow[i]);
        acc += v * v;
    }
    #pragma unroll
    for (int o = 16; o > 0; o >>= 1)
        acc += __shfl_down_sync(0xFFFFFFFF, acc, o);
    int lane = threadIdx.x & 31;
    int wid  = threadIdx.x >> 5;
    if (lane == 0) warp_part[wid] = acc;
    __syncthreads();
    if (wid == 0) {
        int nw = (blockDim.x + 31) >> 5;
        acc = (lane < nw) ? warp_part[lane] : 0.0f;
        #pragma unroll
        for (int o = 16; o > 0; o >>= 1)
            acc += __shfl_down_sync(0xFFFFFFFF, acc, o);
        if (lane == 0) atomicAdd(out0, acc);
    }
}

// ---------------------------------------------------------------------------
// Launch. Inputs: demands, node_embeddings, edge_src, edge_dst, [weights...].
// Output layout: [flow_cost(1), flow(E), fw(E)]. The GNN is provably dead
// code w.r.t. the outputs (uniform per-segment softmax scores).
// ---------------------------------------------------------------------------
extern "C" void kernel_launch(void* const* d_in, const int* in_sizes, int n_in,
                              void* d_out, int out_size) {
    const float* demands = (const float*)d_in[0];   // N x 1
    const int*   src     = (const int*)  d_in[2];   // E
    const int*   dst     = (const int*)  d_in[3];   // E
    const int E = in_sizes[2];
    const int Nn = in_sizes[0];

    float* out  = (float*)d_out;
    float* flow = out + 1;       // E floats (only 4B aligned!)
    float* fw   = out + 1 + E;   // E floats (only 4B aligned!)

    // Can the persistent kernel's GRID blocks be fully co-resident?
    bool use_persist = (E == E_EDGES && Nn == N_NODES);
    if (use_persist) {
        int dev = 0, sms = 0, occ = 0;
        cudaGetDevice(&dev);
        cudaDeviceGetAttribute(&sms, cudaDevAttrMultiProcessorCount, dev);
        cudaOccupancyMaxActiveBlocksPerMultiprocessor(&occ, k_persist, TPB, 0);
        if ((long long)occ * sms < GRID) use_persist = false;
    }

    if (use_persist) {
        k_persist<<<GRID, TPB>>>(src, dst, demands, out);
        return;
    }

    // Fallback: proven multi-kernel path.
    const int T   = 256;
    const int BE  = (E + T - 1) / T;
    const int BE2 = (E / 2 + T) / T;
    const int BN  = (N_NODES + T - 1) / T;

    k_zero<<<BN, T>>>(out);
    k_count<<<BE, T>>>(src, E);
    k_init<<<BE, T>>>(src, flow, fw, E);
    for (int it = 0; it < FLOW_ITERS; ++it) {
        int buf = it & 1;
        k_scatter<<<BE2, T>>>(dst, flow, E, buf);
        k_apply<<<BE2, T>>>(src, fw, demands, flow, E, buf);
    }
    k_cost<<<1024, 256>>>(flow, out, E);
}

// round 11
// speedup vs baseline: 1.1378x; 1.0568x over previous
#include <cuda_runtime.h>
#include <cuda_bf16.h>

// Problem constants (fixed by the reference's setup_inputs)
#define N_NODES  100000
#define E_EDGES  1600000
#define FLOW_ITERS 10

// Persistent-kernel geometry: must be co-resident for the software grid barrier.
#define GRID 592                               // 4 blocks/SM x 148 SMs (measured best)
#define TPB  256
#define TTOT (GRID * TPB)                      // 151,552 threads
#define EPT_FULL (E_EDGES / TTOT)              // 10 full strides
#define EPT (EPT_FULL + 1)                     // 11 (last stride partial)
#define E_TAIL (E_EDGES - EPT_FULL * TTOT)     // 84,480 edges in last stride
#define CHUNK 169                              // ceil(N_NODES / GRID) nodes per block

// Scratch (__device__ globals; no cudaMalloc allowed)
__device__ int      g_deg[N_NODES];            // out-degree (src) — also fallback
__device__ int      g_degd[N_NODES];           // in-degree (dst)
__device__ float    g_invdeg[N_NODES];
__device__ int      g_row[N_NODES + 1];        // CSR row starts (by dst)
__device__ int      g_cursor[N_NODES];
__device__ int      g_col[E_EDGES];            // CSR cols = src of each in-edge
__device__ float    g_v[2][N_NODES];           // v_k = invdeg*relu(inflow_k - d0)
__device__ int      g_btotal[GRID];
__device__ unsigned g_count, g_gen;            // barrier state

// Software grid barrier. The gpu-scope __threadfence() emits CCTL.IVALL on
// sm_103a (B300_MICROARCH), invalidating L1D — validated in R7/R8: plain
// L1-cached loads of cross-SM data are coherent across phases.
__device__ __forceinline__ void gbar() {
    __syncthreads();
    if (threadIdx.x == 0) {
        unsigned old = *(volatile unsigned*)&g_gen;
        __threadfence();
        if (atomicAdd(&g_count, 1u) == GRID - 1) {
            g_count = 0;
            __threadfence();
            atomicAdd(&g_gen, 1u);
        } else {
            while (*(volatile unsigned*)&g_gen == old) { __nanosleep(32); }
        }
        __threadfence();
    }
    __syncthreads();
}

// ---------------------------------------------------------------------------
// Persistent fused kernel, CSR formulation (ZERO atomics in the flow loop):
//   v_0 = invdeg;  v_k = invdeg * relu(A @ v_{k-1} - d0)   (A = in-adjacency)
//   flow = v_10[src],  fw = invdeg[src] = v_0[src]
// Loop iteration = one row pass: gather v_prev[col], sum, store. 1 barrier.
// ---------------------------------------------------------------------------
__global__ void __launch_bounds__(TPB, 4)
k_persist(const int* __restrict__ src_g, const int* __restrict__ dst_g,
          const float* __restrict__ d0, float* __restrict__ out)
{
    const int tid = blockIdx.x * TPB + threadIdx.x;
    float* __restrict__ flow_out = out + 1;
    float* __restrict__ fw_out   = out + 1 + E_EDGES;
    const bool tail_ok = (tid < E_TAIL);

    // Edge payload in registers for the whole kernel.
    int esrc[EPT], edst[EPT];
#pragma unroll
    for (int k = 0; k < EPT_FULL; k++) {
        esrc[k] = __ldg(src_g + tid + k * TTOT);
        edst[k] = __ldg(dst_g + tid + k * TTOT);
    }
    esrc[EPT_FULL] = tail_ok ? __ldg(src_g + tid + EPT_FULL * TTOT) : 0;
    edst[EPT_FULL] = tail_ok ? __ldg(dst_g + tid + EPT_FULL * TTOT) : 0;

    // Phase A: zero histograms + cost.
    if (tid < N_NODES) { g_deg[tid] = 0; g_degd[tid] = 0; }
    if (tid == 0) out[0] = 0.0f;
    gbar();

    // Phase B: out-degree (src) and in-degree (dst) histograms.
#pragma unroll
    for (int k = 0; k < EPT_FULL; k++) {
        atomicAdd(&g_deg[esrc[k]], 1);
        atomicAdd(&g_degd[edst[k]], 1);
    }
    if (tail_ok) {
        atomicAdd(&g_deg[esrc[EPT_FULL]], 1);
        atomicAdd(&g_degd[edst[EPT_FULL]], 1);
    }
    gbar();

    // Phase C1: per-block exclusive scan of in-degrees over this block's
    // CHUNK nodes; stash chunk-local prefix in g_row, block sum in g_btotal.
    // Also: invdeg[n] = 1/(deg_src+1e-9) (bitwise identical to the reference
    // segment softmax: all scores per segment equal -> exp==1, den==deg
    // exactly), and v_0 = invdeg.
    {
        __shared__ int sc[TPB];
        int t = threadIdx.x;
        int n = blockIdx.x * CHUNK + t;
        int dval = (t < CHUNK && n < N_NODES) ? g_degd[n] : 0;
        sc[t] = dval;
        __syncthreads();
#pragma unroll
        for (int off = 1; off < TPB; off <<= 1) {
            int add = (t >= off) ? sc[t - off] : 0;
            __syncthreads();
            sc[t] += add;
            __syncthreads();
        }
        if (t < CHUNK && n < N_NODES) g_row[n] = sc[t] - dval;  // chunk-local
        if (t == 0) g_btotal[blockIdx.x] = sc[TPB - 1];
    }
    if (tid < N_NODES) {
        float iv = 1.0f / ((float)g_deg[tid] + 1e-9f);
        g_invdeg[tid] = iv;
        __stcg(&g_v[0][tid], iv);                 // v_0
    }
    gbar();

    // Phase C2: scan block totals (redundantly per block), add base offset,
    // init cursors.
    {
        __shared__ int bt[1024];
        int t = threadIdx.x;
        for (int i = t; i < 1024; i += TPB) bt[i] = (i < GRID) ? g_btotal[i] : 0;
        __syncthreads();
        int my_tot = bt[blockIdx.x];
        for (int off = 1; off < 1024; off <<= 1) {
            int tmp[1024 / TPB];
#pragma unroll
            for (int i = t, j = 0; i < 1024; i += TPB, j++)
                tmp[j] = (i >= off) ? bt[i - off] : 0;
            __syncthreads();
#pragma unroll
            for (int i = t, j = 0; i < 1024; i += TPB, j++)
                bt[i] += tmp[j];
            __syncthreads();
        }
        int base = bt[blockIdx.x] - my_tot;       // exclusive prefix of totals
        int n = blockIdx.x * CHUNK + t;
        if (t < CHUNK && n < N_NODES) {
            int rs = g_row[n] + base;
            g_row[n] = rs;
            g_cursor[n] = rs;
        }
        if (tid == 0) g_row[N_NODES] = E_EDGES;
    }
    gbar();

    // Phase D: CSR fill (the ONLY remaining per-edge atomics, paid once).
    // Overlap: also emit the fw output (invdeg gather) here.
#pragma unroll
    for (int k = 0; k < EPT; k++) {
        bool ok = (k < EPT_FULL) || tail_ok;
        if (ok) {
            int p = atomicAdd(&g_cursor[edst[k]], 1);
            g_col[p] = esrc[k];
            fw_out[tid + k * TTOT] = g_invdeg[esrc[k]];
        }
    }
    gbar();

    // Phases E (x10): row pass. No atomics: thread r sums v_prev over its
    // in-edges, applies invdeg*relu(sum-d0), one plain store. 1 barrier/iter.
    for (int it = 1; it <= FLOW_ITERS; ++it) {
        const float* __restrict__ vp = g_v[(it - 1) & 1];
        float* __restrict__ vc = g_v[it & 1];
        if (tid < N_NODES) {
            int s = g_row[tid], e = g_row[tid + 1];
            float sum = 0.0f;
#pragma unroll 4
            for (int i = s; i < e; ++i) sum += vp[g_col[i]];
            float vk = g_invdeg[tid] * fmaxf(sum - __ldg(&d0[tid]), 0.0f);
            __stcg(&vc[tid], vk);
        }
        gbar();
    }

    // Epilogue: flow[e] = v_10[src[e]]; cost = sum(flow^2).
    const float* __restrict__ vf = g_v[FLOW_ITERS & 1];
    float acc = 0.0f;
#pragma unroll
    for (int k = 0; k < EPT_FULL; k++) {
        float fl = vf[esrc[k]];
        flow_out[tid + k * TTOT] = fl;
        acc += fl * fl;
    }
    if (tail_ok) {
        float fl = vf[esrc[EPT_FULL]];
        flow_out[tid + EPT_FULL * TTOT] = fl;
        acc += fl * fl;
    }

    __shared__ float warp_part[TPB / 32];
#pragma unroll
    for (int o = 16; o > 0; o >>= 1)
        acc += __shfl_down_sync(0xFFFFFFFF, acc, o);
    int lane = threadIdx.x & 31, wid = threadIdx.x >> 5;
    if (lane == 0) warp_part[wid] = acc;
    __syncthreads();
    if (wid == 0) {
        acc = (lane < TPB / 32) ? warp_part[lane] : 0.0f;
#pragma unroll
        for (int o = 16; o > 0; o >>= 1)
            acc += __shfl_down_sync(0xFFFFFFFF, acc, o);
        if (lane == 0) atomicAdd(out, acc);
    }
}

// ======================= Fallback path (proven R3 kernels) ==================
__device__ float g_inflow2[2][N_NODES];

__global__ void k_zero(float* __restrict__ out0) {
    int i = blockIdx.x * blockDim.x + threadIdx.x;
    if (i < N_NODES) {
        g_deg[i] = 0;
        g_inflow2[0][i] = 0.0f;
        g_inflow2[1][i] = 0.0f;
    }
    if (i == 0) *out0 = 0.0f;
}

__global__ void k_count(const int* __restrict__ src, int E) {
    int i = blockIdx.x * blockDim.x + threadIdx.x;
    if (i < E) atomicAdd(&g_deg[__ldg(&src[i])], 1);
}

__global__ void k_init(const int* __restrict__ src,
                       float* __restrict__ flow,
                       float* __restrict__ fw, int E) {
    int i = blockIdx.x * blockDim.x + threadIdx.x;
    if (i < E) {
        float den = (float)g_deg[__ldg(&src[i])] + 1e-9f;
        float f = 1.0f / den;
        fw[i]   = f;
        flow[i] = f;
    }
}

__global__ void k_scatter(const int* __restrict__ dst,
                          const float* __restrict__ flow, int E, int buf) {
    int i2 = blockIdx.x * blockDim.x + threadIdx.x;
    int i  = i2 * 2;
    if (i + 1 < E) {
        int2  d  = *(const int2*)(dst + i);
        float f0 = __ldg(&flow[i]);
        float f1 = __ldg(&flow[i + 1]);
        atomicAdd(&g_inflow2[buf][d.x], f0);
        atomicAdd(&g_inflow2[buf][d.y], f1);
    } else if (i < E) {
        atomicAdd(&g_inflow2[buf][__ldg(&dst[i])], __ldg(&flow[i]));
    }
}

__global__ void k_apply(const int* __restrict__ src,
                        const float* __restrict__ fw,
                        const float* __restrict__ d0,
                        float* __restrict__ flow, int E, int buf) {
    int i2 = blockIdx.x * blockDim.x + threadIdx.x;
    int i  = i2 * 2;
    const float* __restrict__ infl = g_inflow2[buf];
    if (i + 1 < E) {
        int2  s  = *(const int2*)(src + i);
        float w0 = __ldg(&fw[i]);
        float w1 = __ldg(&fw[i + 1]);
        float a0 = fmaxf(__ldg(&infl[s.x]) - __ldg(&d0[s.x]), 0.0f);
        float a1 = fmaxf(__ldg(&infl[s.y]) - __ldg(&d0[s.y]), 0.0f);
        flow[i]     = w0 * a0;
        flow[i + 1] = w1 * a1;
    } else if (i < E) {
        int s = __ldg(&src[i]);
        float a = fmaxf(__ldg(&infl[s]) - __ldg(&d0[s]), 0.0f);
        flow[i] = __ldg(&fw[i]) * a;
    }
    if (i2 < N_NODES) g_inflow2[buf ^ 1][i2] = 0.0f;
}

__global__ void k_cost(const float* __restrict__ flow, float* __restrict__ out0, int E) {
    __shared__ float warp_part[32];
    float acc = 0.0f;
    for (int i = blockIdx.x * blockDim.x + threadIdx.x; i < E;
         i += gridDim.x * blockDim.x) {
        float v = __ldg(&flow[i]);
        acc += v * v;
    }
    #pragma unroll
    for (int o = 16; o > 0; o >>= 1)
        acc += __shfl_down_sync(0xFFFFFFFF, acc, o);
    int lane = threadIdx.x & 31;
    int wid  = threadIdx.x >> 5;
    if (lane == 0) warp_part[wid] = acc;
    __syncthreads();
    if (wid == 0) {
        int nw = (blockDim.x + 31) >> 5;
        acc = (lane < nw) ? warp_part[lane] : 0.0f;
        #pragma unroll
        for (int o = 16; o > 0; o >>= 1)
            acc += __shfl_down_sync(0xFFFFFFFF, acc, o);
        if (lane == 0) atomicAdd(out0, acc);
    }
}

// ---------------------------------------------------------------------------
// Launch. Inputs: demands, node_embeddings, edge_src, edge_dst, [weights...].
// Output layout: [flow_cost(1), flow(E), fw(E)]. The GNN is provably dead
// code w.r.t. the outputs (uniform per-segment softmax scores).
// ---------------------------------------------------------------------------
extern "C" void kernel_launch(void* const* d_in, const int* in_sizes, int n_in,
                              void* d_out, int out_size) {
    const float* demands = (const float*)d_in[0];   // N x 1
    const int*   src     = (const int*)  d_in[2];   // E
    const int*   dst     = (const int*)  d_in[3];   // E
    const int E = in_sizes[2];
    const int Nn = in_sizes[0];

    float* out  = (float*)d_out;
    float* flow = out + 1;       // E floats (only 4B aligned!)
    float* fw   = out + 1 + E;   // E floats (only 4B aligned!)

    // Can the persistent kernel's GRID blocks be fully co-resident?
    bool use_persist = (E == E_EDGES && Nn == N_NODES);
    if (use_persist) {
        int dev = 0, sms = 0, occ = 0;
        cudaGetDevice(&dev);
        cudaDeviceGetAttribute(&sms, cudaDevAttrMultiProcessorCount, dev);
        cudaOccupancyMaxActiveBlocksPerMultiprocessor(&occ, k_persist, TPB, 0);
        if ((long long)occ * sms < GRID) use_persist = false;
    }

    if (use_persist) {
        k_persist<<<GRID, TPB>>>(src, dst, demands, out);
        return;
    }

    // Fallback: proven multi-kernel path.
    const int T   = 256;
    const int BE  = (E + T - 1) / T;
    const int BE2 = (E / 2 + T) / T;
    const int BN  = (N_NODES + T - 1) / T;

    k_zero<<<BN, T>>>(out);
    k_count<<<BE, T>>>(src, E);
    k_init<<<BE, T>>>(src, flow, fw, E);
    for (int it = 0; it < FLOW_ITERS; ++it) {
        int buf = it & 1;
        k_scatter<<<BE2, T>>>(dst, flow, E, buf);
        k_apply<<<BE2, T>>>(src, fw, demands, flow, E, buf);
    }
    k_cost<<<1024, 256>>>(flow, out, E);
}

// round 12
// speedup vs baseline: 1.2812x; 1.1260x over previous
#include <cuda_runtime.h>
#include <cuda_bf16.h>

// Problem constants (fixed by the reference's setup_inputs)
#define N_NODES  100000
#define E_EDGES  1600000
#define FLOW_ITERS 10

// Persistent-kernel geometry: must be co-resident for the software grid barrier.
#define GRID 592                               // 4 blocks/SM x 148 SMs (measured best)
#define TPB  256
#define TTOT (GRID * TPB)                      // 151,552 threads
#define EPT_FULL (E_EDGES / TTOT)              // 10 full strides
#define EPT (EPT_FULL + 1)                     // 11 (last stride partial)
#define E_TAIL (E_EDGES - EPT_FULL * TTOT)     // 84,480 edges in last stride
#define NPB  169                               // nodes per block: 592*169 >= N
#define SMEM_COLS 4096                         // block col-slice cap (mean 2704, sd 52)

// Scratch (__device__ globals; zero-initialized at module load; the persistent
// epilogue re-zeroes the accumulating ones for graph-replay determinism)
__device__ int      g_deg[N_NODES];            // out-degree (src)
__device__ int      g_degd[N_NODES];           // in-degree (dst)
__device__ float    g_invdeg[N_NODES];
__device__ int      g_row[N_NODES];            // CSR row starts (by dst)
__device__ int      g_cursor[N_NODES];
__device__ int      g_col[E_EDGES];            // CSR cols = src of each in-edge
__device__ float    g_v[2][N_NODES];           // v_k = invdeg*relu(inflow_k - d0)
__device__ int      g_base;                    // atomic CSR base allocator
__device__ unsigned g_count, g_gen;            // barrier state

// Software grid barrier. gpu-scope __threadfence() emits CCTL.IVALL on sm_103a,
// so plain L1-cached loads of cross-SM data are coherent across phases
// (validated R7/R8/R11: rel_err ~5e-7). Generation-relative, so g_gen may
// carry over between graph replays.
__device__ __forceinline__ void gbar() {
    __syncthreads();
    if (threadIdx.x == 0) {
        unsigned old = *(volatile unsigned*)&g_gen;
        __threadfence();
        if (atomicAdd(&g_count, 1u) == GRID - 1) {
            g_count = 0;
            __threadfence();
            atomicAdd(&g_gen, 1u);
        } else {
            while (*(volatile unsigned*)&g_gen == old) { __nanosleep(32); }
        }
        __threadfence();
    }
    __syncthreads();
}

// ---------------------------------------------------------------------------
// Persistent fused kernel, CSR formulation, balanced ownership:
//   v_0 = invdeg;  v_k = invdeg * relu(A @ v_{k-1} - d0)   (A = in-adjacency)
//   flow = v_10[src],  fw = invdeg[src]
// Each block owns exactly NPB consecutive nodes; its CSR col slice is staged
// to SHARED once and reused for all 10 iterations; per-node row metadata
// lives in registers. Loop body: LDS col -> LDG v -> add. 13 barriers total.
// ---------------------------------------------------------------------------
__global__ void __launch_bounds__(TPB, 4)
k_persist(const int* __restrict__ src_g, const int* __restrict__ dst_g,
          const float* __restrict__ d0, float* __restrict__ out)
{
    __shared__ int   s_col[SMEM_COLS];
    __shared__ int   s_scan[TPB];
    __shared__ int   s_base_sh;
    __shared__ float s_wred[TPB / 32];

    const int b   = blockIdx.x;
    const int t   = threadIdx.x;
    const int tid = b * TPB + t;
    float* __restrict__ flow_out = out + 1;
    float* __restrict__ fw_out   = out + 1 + E_EDGES;
    const bool tail_ok = (tid < E_TAIL);

    // Edge payload in registers for the whole kernel.
    int esrc[EPT], edst[EPT];
#pragma unroll
    for (int k = 0; k < EPT_FULL; k++) {
        esrc[k] = __ldg(src_g + tid + k * TTOT);
        edst[k] = __ldg(dst_g + tid + k * TTOT);
    }
    esrc[EPT_FULL] = tail_ok ? __ldg(src_g + tid + EPT_FULL * TTOT) : 0;
    edst[EPT_FULL] = tail_ok ? __ldg(dst_g + tid + EPT_FULL * TTOT) : 0;

    // Phase 1: histograms (g_deg/g_degd are zero at entry: zero-init on first
    // run, re-zeroed in epilogue for replays). Also reset cost accumulator.
    if (tid == 0) out[0] = 0.0f;
#pragma unroll
    for (int k = 0; k < EPT_FULL; k++) {
        atomicAdd(&g_deg[esrc[k]], 1);
        atomicAdd(&g_degd[edst[k]], 1);
    }
    if (tail_ok) {
        atomicAdd(&g_deg[esrc[EPT_FULL]], 1);
        atomicAdd(&g_degd[edst[EPT_FULL]], 1);
    }
    gbar();                                            // barrier 1

    // Phase 2 (merged scan): per-block scan of owned in-degrees; block claims
    // a contiguous CSR range via one atomicAdd on g_base (zero at entry).
    // Rows of a block are contiguous; cross-block base order is arbitrary
    // (valid CSR; within-row add order already nondeterministic via cursors).
    // Also: invdeg = 1/(deg+1e-9) — bitwise identical to the reference
    // segment softmax (equal scores per segment -> exp==1, den==deg exactly);
    // v_0 = invdeg.
    const int  n   = b * NPB + t;                      // owned node
    const bool own = (t < NPB) && (n < N_NODES);
    int my_deg = own ? g_degd[n] : 0;
    {
        s_scan[t] = my_deg;
        __syncthreads();
#pragma unroll
        for (int off = 1; off < TPB; off <<= 1) {
            int add = (t >= off) ? s_scan[t - off] : 0;
            __syncthreads();
            s_scan[t] += add;
            __syncthreads();
        }
        if (t == 0) s_base_sh = atomicAdd(&g_base, s_scan[TPB - 1]);
        __syncthreads();
    }
    const int blk_base = s_base_sh;
    const int blk_tot  = s_scan[TPB - 1];
    const int my_loc   = s_scan[t] - my_deg;           // local CSR offset
    if (own) {
        int rs = blk_base + my_loc;
        g_row[n]    = rs;
        g_cursor[n] = rs;
    }
    if (tid < N_NODES) {
        float iv = 1.0f / ((float)g_deg[tid] + 1e-9f);
        g_invdeg[tid] = iv;
        __stcg(&g_v[0][tid], iv);                      // v_0
    }
    gbar();                                            // barrier 2

    // Phase 3: CSR fill (the only per-edge atomics, paid once) + fw output.
#pragma unroll
    for (int k = 0; k < EPT; k++) {
        bool ok = (k < EPT_FULL) || tail_ok;
        if (ok) {
            int p = atomicAdd(&g_cursor[edst[k]], 1);
            g_col[p] = esrc[k];
            fw_out[tid + k * TTOT] = g_invdeg[esrc[k]];
        }
    }
    gbar();                                            // barrier 3

    // Stage this block's contiguous col slice into SHARED (once, reused x10),
    // and hoist per-node metadata to registers.
    const bool use_smem = (blk_tot <= SMEM_COLS);
    if (use_smem) {
        for (int i = t; i < blk_tot; i += TPB) s_col[i] = g_col[blk_base + i];
    }
    float my_iv = 0.0f, my_d0 = 0.0f;
    if (own) {
        my_iv = g_invdeg[n];
        my_d0 = __ldg(&d0[n]);
    }
    __syncthreads();

    // Phases 4..13: row passes. No atomics; loop body is LDS col -> LDG v.
    for (int it = 1; it <= FLOW_ITERS; ++it) {
        const float* __restrict__ vp = g_v[(it - 1) & 1];
        float* __restrict__ vc = g_v[it & 1];
        if (own) {
            float sum = 0.0f;
            if (use_smem) {
                int s = my_loc, e = my_loc + my_deg;
                int i = s;
                for (; i + 4 <= e; i += 4) {
                    float a0 = vp[s_col[i]];
                    float a1 = vp[s_col[i + 1]];
                    float a2 = vp[s_col[i + 2]];
                    float a3 = vp[s_col[i + 3]];
                    sum += (a0 + a1) + (a2 + a3);
                }
                for (; i < e; ++i) sum += vp[s_col[i]];
            } else {                                   // pathological fallback
                int s = blk_base + my_loc, e = s + my_deg;
                for (int i = s; i < e; ++i) sum += vp[g_col[i]];
            }
            __stcg(&vc[n], my_iv * fmaxf(sum - my_d0, 0.0f));
        }
        gbar();                                        // barriers 4..13
    }

    // Epilogue: flow[e] = v_10[src[e]] (v_10 lives in g_v[0]); cost = sum sq.
    // Also re-zero the accumulating globals for the next graph replay.
    const float* __restrict__ vf = g_v[FLOW_ITERS & 1];
    float acc = 0.0f;
#pragma unroll
    for (int k = 0; k < EPT_FULL; k++) {
        float fl = vf[esrc[k]];
        flow_out[tid + k * TTOT] = fl;
        acc += fl * fl;
    }
    if (tail_ok) {
        float fl = vf[esrc[EPT_FULL]];
        flow_out[tid + EPT_FULL * TTOT] = fl;
        acc += fl * fl;
    }
    if (tid < N_NODES) { g_deg[tid] = 0; g_degd[tid] = 0; }
    if (tid == 0) g_base = 0;

#pragma unroll
    for (int o = 16; o > 0; o >>= 1)
        acc += __shfl_down_sync(0xFFFFFFFF, acc, o);
    int lane = t & 31, wid = t >> 5;
    if (lane == 0) s_wred[wid] = acc;
    __syncthreads();
    if (wid == 0) {
        acc = (lane < TPB / 32) ? s_wred[lane] : 0.0f;
#pragma unroll
        for (int o = 16; o > 0; o >>= 1)
            acc += __shfl_down_sync(0xFFFFFFFF, acc, o);
        if (lane == 0) atomicAdd(out, acc);
    }
}

// ======================= Fallback path (proven R3 kernels) ==================
__device__ float g_inflow2[2][N_NODES];

__global__ void k_zero(float* __restrict__ out0) {
    int i = blockIdx.x * blockDim.x + threadIdx.x;
    if (i < N_NODES) {
        g_deg[i] = 0;
        g_inflow2[0][i] = 0.0f;
        g_inflow2[1][i] = 0.0f;
    }
    if (i == 0) *out0 = 0.0f;
}

__global__ void k_count(const int* __restrict__ src, int E) {
    int i = blockIdx.x * blockDim.x + threadIdx.x;
    if (i < E) atomicAdd(&g_deg[__ldg(&src[i])], 1);
}

__global__ void k_init(const int* __restrict__ src,
                       float* __restrict__ flow,
                       float* __restrict__ fw, int E) {
    int i = blockIdx.x * blockDim.x + threadIdx.x;
    if (i < E) {
        float den = (float)g_deg[__ldg(&src[i])] + 1e-9f;
        float f = 1.0f / den;
        fw[i]   = f;
        flow[i] = f;
    }
}

__global__ void k_scatter(const int* __restrict__ dst,
                          const float* __restrict__ flow, int E, int buf) {
    int i2 = blockIdx.x * blockDim.x + threadIdx.x;
    int i  = i2 * 2;
    if (i + 1 < E) {
        int2  d  = *(const int2*)(dst + i);
        float f0 = __ldg(&flow[i]);
        float f1 = __ldg(&flow[i + 1]);
        atomicAdd(&g_inflow2[buf][d.x], f0);
        atomicAdd(&g_inflow2[buf][d.y], f1);
    } else if (i < E) {
        atomicAdd(&g_inflow2[buf][__ldg(&dst[i])], __ldg(&flow[i]));
    }
}

__global__ void k_apply(const int* __restrict__ src,
                        const float* __restrict__ fw,
                        const float* __restrict__ d0,
                        float* __restrict__ flow, int E, int buf) {
    int i2 = blockIdx.x * blockDim.x + threadIdx.x;
    int i  = i2 * 2;
    const float* __restrict__ infl = g_inflow2[buf];
    if (i + 1 < E) {
        int2  s  = *(const int2*)(src + i);
        float w0 = __ldg(&fw[i]);
        float w1 = __ldg(&fw[i + 1]);
        float a0 = fmaxf(__ldg(&infl[s.x]) - __ldg(&d0[s.x]), 0.0f);
        float a1 = fmaxf(__ldg(&infl[s.y]) - __ldg(&d0[s.y]), 0.0f);
        flow[i]     = w0 * a0;
        flow[i + 1] = w1 * a1;
    } else if (i < E) {
        int s = __ldg(&src[i]);
        float a = fmaxf(__ldg(&infl[s]) - __ldg(&d0[s]), 0.0f);
        flow[i] = __ldg(&fw[i]) * a;
    }
    if (i2 < N_NODES) g_inflow2[buf ^ 1][i2] = 0.0f;
}

__global__ void k_cost(const float* __restrict__ flow, float* __restrict__ out0, int E) {
    __shared__ float warp_part[32];
    float acc = 0.0f;
    for (int i = blockIdx.x * blockDim.x + threadIdx.x; i < E;
         i += gridDim.x * blockDim.x) {
        float v = __ldg(&flow[i]);
        acc += v * v;
    }
    #pragma unroll
    for (int o = 16; o > 0; o >>= 1)
        acc += __shfl_down_sync(0xFFFFFFFF, acc, o);
    int lane = threadIdx.x & 31;
    int wid  = threadIdx.x >> 5;
    if (lane == 0) warp_part[wid] = acc;
    __syncthreads();
    if (wid == 0) {
        int nw = (blockDim.x + 31) >> 5;
        acc = (lane < nw) ? warp_part[lane] : 0.0f;
        #pragma unroll
        for (int o = 16; o > 0; o >>= 1)
            acc += __shfl_down_sync(0xFFFFFFFF, acc, o);
        if (lane == 0) atomicAdd(out0, acc);
    }
}

// ---------------------------------------------------------------------------
// Launch. Inputs: demands, node_embeddings, edge_src, edge_dst, [weights...].
// Output layout: [flow_cost(1), flow(E), fw(E)]. The GNN is provably dead
// code w.r.t. the outputs (uniform per-segment softmax scores).
// ---------------------------------------------------------------------------
extern "C" void kernel_launch(void* const* d_in, const int* in_sizes, int n_in,
                              void* d_out, int out_size) {
    const float* demands = (const float*)d_in[0];   // N x 1
    const int*   src     = (const int*)  d_in[2];   // E
    const int*   dst     = (const int*)  d_in[3];   // E
    const int E = in_sizes[2];
    const int Nn = in_sizes[0];

    float* out  = (float*)d_out;
    float* flow = out + 1;       // E floats (only 4B aligned!)
    float* fw   = out + 1 + E;   // E floats (only 4B aligned!)

    // Can the persistent kernel's GRID blocks be fully co-resident?
    bool use_persist = (E == E_EDGES && Nn == N_NODES);
    if (use_persist) {
        int dev = 0, sms = 0, occ = 0;
        cudaGetDevice(&dev);
        cudaDeviceGetAttribute(&sms, cudaDevAttrMultiProcessorCount, dev);
        cudaOccupancyMaxActiveBlocksPerMultiprocessor(&occ, k_persist, TPB, 0);
        if ((long long)occ * sms < GRID) use_persist = false;
    }

    if (use_persist) {
        k_persist<<<GRID, TPB>>>(src, dst, demands, out);
        return;
    }

    // Fallback: proven multi-kernel path.
    const int T   = 256;
    const int BE  = (E + T - 1) / T;
    const int BE2 = (E / 2 + T) / T;
    const int BN  = (N_NODES + T - 1) / T;

    k_zero<<<BN, T>>>(out);
    k_count<<<BE, T>>>(src, E);
    k_init<<<BE, T>>>(src, flow, fw, E);
    for (int it = 0; it < FLOW_ITERS; ++it) {
        int buf = it & 1;
        k_scatter<<<BE2, T>>>(dst, flow, E, buf);
        k_apply<<<BE2, T>>>(src, fw, demands, flow, E, buf);
    }
    k_cost<<<1024, 256>>>(flow, out, E);
}

// round 13
// speedup vs baseline: 1.3145x; 1.0260x over previous
#include <cuda_runtime.h>
#include <cuda_bf16.h>

// Problem constants (fixed by the reference's setup_inputs)
#define N_NODES  100000
#define E_EDGES  1600000
#define FLOW_ITERS 10

// Persistent-kernel geometry: must be co-resident for the software grid barrier.
#define GRID 592                               // 4 blocks/SM x 148 SMs (measured best)
#define TPB  256
#define TTOT (GRID * TPB)                      // 151,552 threads
#define EPT_FULL (E_EDGES / TTOT)              // 10 full strides
#define EPT (EPT_FULL + 1)                     // 11 (last stride partial)
#define E_TAIL (E_EDGES - EPT_FULL * TTOT)     // 84,480 edges in last stride
#define NPB  169                               // nodes per block: 592*169 >= N
#define SMEM_COLS 4096                         // block col-slice cap (mean 2704, sd ~52)

// Scratch (__device__ globals; zero-initialized at module load; the persistent
// epilogue re-zeroes the accumulating ones for graph-replay determinism)
__device__ int      g_deg[N_NODES];            // out-degree (src)
__device__ int      g_degd[N_NODES];           // in-degree (dst)
__device__ float    g_invdeg[N_NODES];
__device__ int      g_row[N_NODES];            // CSR row starts (by dst)
__device__ int      g_cursor[N_NODES];
__device__ int      g_col[E_EDGES];            // CSR cols = src of each in-edge
__device__ float    g_v[2][N_NODES];           // v_k = invdeg*relu(inflow_k - d0)
__device__ int      g_base;                    // atomic CSR base allocator
__device__ unsigned g_count, g_gen;            // barrier state

// Software grid barrier. gpu-scope __threadfence() emits CCTL.IVALL on sm_103a,
// so plain L1-cached loads of cross-SM data are coherent across phases
// (validated R7/R8/R11/R12: rel_err ~3-7e-7). Generation-relative, so g_gen
// may carry over between graph replays.
__device__ __forceinline__ void gbar() {
    __syncthreads();
    if (threadIdx.x == 0) {
        unsigned old = *(volatile unsigned*)&g_gen;
        __threadfence();
        if (atomicAdd(&g_count, 1u) == GRID - 1) {
            g_count = 0;
            __threadfence();
            atomicAdd(&g_gen, 1u);
        } else {
            while (*(volatile unsigned*)&g_gen == old) { __nanosleep(32); }
        }
        __threadfence();
    }
    __syncthreads();
}

// ---------------------------------------------------------------------------
// Persistent fused kernel, CSR formulation, fully balanced row pass:
//   v_0 = invdeg;  v_k = invdeg * relu(A @ v_{k-1} - d0)   (A = in-adjacency)
//   flow = v_10[src],  fw = invdeg[src]
// Each block owns NPB consecutive nodes. Its CSR col slice + an edge->owner
// map live in SHARED (staged once). Every iteration ALL 256 threads gather an
// even 1/256 slice of the block's edges (run-coalesced smem atomics into
// s_acc), then owners apply the node update. 13 global barriers total.
// ---------------------------------------------------------------------------
__global__ void __launch_bounds__(TPB, 4)
k_persist(const int* __restrict__ src_g, const int* __restrict__ dst_g,
          const float* __restrict__ d0, float* __restrict__ out)
{
    __shared__ int            s_col[SMEM_COLS];
    __shared__ unsigned short s_node[SMEM_COLS];
    __shared__ int            s_scan[TPB];
    __shared__ float          s_acc[NPB];
    __shared__ int            s_base_sh;
    __shared__ float          s_wred[TPB / 32];

    const int b   = blockIdx.x;
    const int t   = threadIdx.x;
    const int tid = b * TPB + t;
    float* __restrict__ flow_out = out + 1;
    float* __restrict__ fw_out   = out + 1 + E_EDGES;
    const bool tail_ok = (tid < E_TAIL);

    // Edge payload in registers for the whole kernel.
    int esrc[EPT], edst[EPT];
#pragma unroll
    for (int k = 0; k < EPT_FULL; k++) {
        esrc[k] = __ldg(src_g + tid + k * TTOT);
        edst[k] = __ldg(dst_g + tid + k * TTOT);
    }
    esrc[EPT_FULL] = tail_ok ? __ldg(src_g + tid + EPT_FULL * TTOT) : 0;
    edst[EPT_FULL] = tail_ok ? __ldg(dst_g + tid + EPT_FULL * TTOT) : 0;

    // Phase 1: histograms (g_deg/g_degd zero at entry: zero-init on first run,
    // re-zeroed in epilogue for replays). Also reset cost accumulator.
    if (tid == 0) out[0] = 0.0f;
#pragma unroll
    for (int k = 0; k < EPT_FULL; k++) {
        atomicAdd(&g_deg[esrc[k]], 1);
        atomicAdd(&g_degd[edst[k]], 1);
    }
    if (tail_ok) {
        atomicAdd(&g_deg[esrc[EPT_FULL]], 1);
        atomicAdd(&g_degd[edst[EPT_FULL]], 1);
    }
    gbar();                                            // barrier 1

    // Phase 2 (merged scan): per-block scan of owned in-degrees; block claims
    // a contiguous CSR range via one atomicAdd on g_base. invdeg = 1/(deg+1e-9)
    // is bitwise identical to the reference segment softmax (equal scores per
    // segment -> exp==1, den==deg exactly); v_0 = invdeg.
    const int  n   = b * NPB + t;                      // owned node
    const bool own = (t < NPB) && (n < N_NODES);
    int my_deg = own ? g_degd[n] : 0;
    {
        s_scan[t] = my_deg;
        __syncthreads();
#pragma unroll
        for (int off = 1; off < TPB; off <<= 1) {
            int add = (t >= off) ? s_scan[t - off] : 0;
            __syncthreads();
            s_scan[t] += add;
            __syncthreads();
        }
        if (t == 0) s_base_sh = atomicAdd(&g_base, s_scan[TPB - 1]);
        __syncthreads();
    }
    const int blk_base = s_base_sh;
    const int blk_tot  = s_scan[TPB - 1];
    const int my_loc   = s_scan[t] - my_deg;           // local CSR offset
    const bool use_smem = (blk_tot <= SMEM_COLS);
    if (own) {
        int rs = blk_base + my_loc;
        g_row[n]    = rs;
        g_cursor[n] = rs;
    }
    if (tid < N_NODES) {
        float iv = 1.0f / ((float)g_deg[tid] + 1e-9f);
        g_invdeg[tid] = iv;
        __stcg(&g_v[0][tid], iv);                      // v_0
    }
    gbar();                                            // barrier 2

    // Phase 3: CSR fill (the only per-edge atomics, paid once) + fw output.
    // Overlap: owners also write the block-local edge->owner map (pure smem,
    // independent of the global fill).
    if (own && use_smem) {
        for (int j = 0; j < my_deg; ++j)
            s_node[my_loc + j] = (unsigned short)t;
    }
#pragma unroll
    for (int k = 0; k < EPT; k++) {
        bool ok = (k < EPT_FULL) || tail_ok;
        if (ok) {
            int p = atomicAdd(&g_cursor[edst[k]], 1);
            g_col[p] = esrc[k];
            fw_out[tid + k * TTOT] = g_invdeg[esrc[k]];
        }
    }
    gbar();                                            // barrier 3

    // Stage this block's contiguous col slice into SHARED (once, reused x10),
    // hoist per-node metadata to registers, compute this thread's edge slice.
    if (use_smem) {
        for (int i = t; i < blk_tot; i += TPB) s_col[i] = g_col[blk_base + i];
    }
    float my_iv = 0.0f, my_d0 = 0.0f;
    if (own) {
        my_iv = g_invdeg[n];
        my_d0 = __ldg(&d0[n]);
    }
    const int lo = (blk_tot * t) >> 8;                 // even 1/256 edge slice
    const int hi = (blk_tot * (t + 1)) >> 8;
    __syncthreads();

    // Phases 4..13: balanced row passes. ALL 256 threads gather; contributions
    // run-coalesced into s_acc via smem atomics (~2-3 per thread); owners
    // finish the node update. Gathers hit L2 directly (v changes every phase).
    for (int it = 1; it <= FLOW_ITERS; ++it) {
        const float* __restrict__ vp = g_v[(it - 1) & 1];
        float* __restrict__ vc = g_v[it & 1];

        if (t < NPB) s_acc[t] = 0.0f;
        __syncthreads();

        if (use_smem) {
            float run = 0.0f;
            int   cur = -1;
            for (int i = lo; i < hi; ++i) {
                int   nd  = s_node[i];
                float val = vp[s_col[i]];
                if (nd != cur) {
                    if (cur >= 0) atomicAdd(&s_acc[cur], run);
                    cur = nd;
                    run = val;
                } else {
                    run += val;
                }
            }
            if (cur >= 0) atomicAdd(&s_acc[cur], run);
        } else if (own) {                              // pathological fallback
            int s = blk_base + my_loc, e = s + my_deg;
            float sum = 0.0f;
            for (int i = s; i < e; ++i) sum += vp[g_col[i]];
            s_acc[t] = sum;
        }
        __syncthreads();

        if (own) __stcg(&vc[n], my_iv * fmaxf(s_acc[t] - my_d0, 0.0f));
        gbar();                                        // barriers 4..13
    }

    // Epilogue: flow[e] = v_10[src[e]]; cost = sum(flow^2).
    // Also re-zero the accumulating globals for the next graph replay.
    const float* __restrict__ vf = g_v[FLOW_ITERS & 1];
    float acc = 0.0f;
#pragma unroll
    for (int k = 0; k < EPT_FULL; k++) {
        float fl = vf[esrc[k]];
        flow_out[tid + k * TTOT] = fl;
        acc += fl * fl;
    }
    if (tail_ok) {
        float fl = vf[esrc[EPT_FULL]];
        flow_out[tid + EPT_FULL * TTOT] = fl;
        acc += fl * fl;
    }
    if (tid < N_NODES) { g_deg[tid] = 0; g_degd[tid] = 0; }
    if (tid == 0) g_base = 0;

#pragma unroll
    for (int o = 16; o > 0; o >>= 1)
        acc += __shfl_down_sync(0xFFFFFFFF, acc, o);
    int lane = t & 31, wid = t >> 5;
    if (lane == 0) s_wred[wid] = acc;
    __syncthreads();
    if (wid == 0) {
        acc = (lane < TPB / 32) ? s_wred[lane] : 0.0f;
#pragma unroll
        for (int o = 16; o > 0; o >>= 1)
            acc += __shfl_down_sync(0xFFFFFFFF, acc, o);
        if (lane == 0) atomicAdd(out, acc);
    }
}

// ======================= Fallback path (proven R3 kernels) ==================
__device__ float g_inflow2[2][N_NODES];

__global__ void k_zero(float* __restrict__ out0) {
    int i = blockIdx.x * blockDim.x + threadIdx.x;
    if (i < N_NODES) {
        g_deg[i] = 0;
        g_inflow2[0][i] = 0.0f;
        g_inflow2[1][i] = 0.0f;
    }
    if (i == 0) *out0 = 0.0f;
}

__global__ void k_count(const int* __restrict__ src, int E) {
    int i = blockIdx.x * blockDim.x + threadIdx.x;
    if (i < E) atomicAdd(&g_deg[__ldg(&src[i])], 1);
}

__global__ void k_init(const int* __restrict__ src,
                       float* __restrict__ flow,
                       float* __restrict__ fw, int E) {
    int i = blockIdx.x * blockDim.x + threadIdx.x;
    if (i < E) {
        float den = (float)g_deg[__ldg(&src[i])] + 1e-9f;
        float f = 1.0f / den;
        fw[i]   = f;
        flow[i] = f;
    }
}

__global__ void k_scatter(const int* __restrict__ dst,
                          const float* __restrict__ flow, int E, int buf) {
    int i2 = blockIdx.x * blockDim.x + threadIdx.x;
    int i  = i2 * 2;
    if (i + 1 < E) {
        int2  d  = *(const int2*)(dst + i);
        float f0 = __ldg(&flow[i]);
        float f1 = __ldg(&flow[i + 1]);
        atomicAdd(&g_inflow2[buf][d.x], f0);
        atomicAdd(&g_inflow2[buf][d.y], f1);
    } else if (i < E) {
        atomicAdd(&g_inflow2[buf][__ldg(&dst[i])], __ldg(&flow[i]));
    }
}

__global__ void k_apply(const int* __restrict__ src,
                        const float* __restrict__ fw,
                        const float* __restrict__ d0,
                        float* __restrict__ flow, int E, int buf) {
    int i2 = blockIdx.x * blockDim.x + threadIdx.x;
    int i  = i2 * 2;
    const float* __restrict__ infl = g_inflow2[buf];
    if (i + 1 < E) {
        int2  s  = *(const int2*)(src + i);
        float w0 = __ldg(&fw[i]);
        float w1 = __ldg(&fw[i + 1]);
        float a0 = fmaxf(__ldg(&infl[s.x]) - __ldg(&d0[s.x]), 0.0f);
        float a1 = fmaxf(__ldg(&infl[s.y]) - __ldg(&d0[s.y]), 0.0f);
        flow[i]     = w0 * a0;
        flow[i + 1] = w1 * a1;
    } else if (i < E) {
        int s = __ldg(&src[i]);
        float a = fmaxf(__ldg(&infl[s]) - __ldg(&d0[s]), 0.0f);
        flow[i] = __ldg(&fw[i]) * a;
    }
    if (i2 < N_NODES) g_inflow2[buf ^ 1][i2] = 0.0f;
}

__global__ void k_cost(const float* __restrict__ flow, float* __restrict__ out0, int E) {
    __shared__ float warp_part[32];
    float acc = 0.0f;
    for (int i = blockIdx.x * blockDim.x + threadIdx.x; i < E;
         i += gridDim.x * blockDim.x) {
        float v = __ldg(&flow[i]);
        acc += v * v;
    }
    #pragma unroll
    for (int o = 16; o > 0; o >>= 1)
        acc += __shfl_down_sync(0xFFFFFFFF, acc, o);
    int lane = threadIdx.x & 31;
    int wid  = threadIdx.x >> 5;
    if (lane == 0) warp_part[wid] = acc;
    __syncthreads();
    if (wid == 0) {
        int nw = (blockDim.x + 31) >> 5;
        acc = (lane < nw) ? warp_part[lane] : 0.0f;
        #pragma unroll
        for (int o = 16; o > 0; o >>= 1)
            acc += __shfl_down_sync(0xFFFFFFFF, acc, o);
        if (lane == 0) atomicAdd(out0, acc);
    }
}

// ---------------------------------------------------------------------------
// Launch. Inputs: demands, node_embeddings, edge_src, edge_dst, [weights...].
// Output layout: [flow_cost(1), flow(E), fw(E)]. The GNN is provably dead
// code w.r.t. the outputs (uniform per-segment softmax scores).
// ---------------------------------------------------------------------------
extern "C" void kernel_launch(void* const* d_in, const int* in_sizes, int n_in,
                              void* d_out, int out_size) {
    const float* demands = (const float*)d_in[0];   // N x 1
    const int*   src     = (const int*)  d_in[2];   // E
    const int*   dst     = (const int*)  d_in[3];   // E
    const int E = in_sizes[2];
    const int Nn = in_sizes[0];

    float* out  = (float*)d_out;
    float* flow = out + 1;       // E floats (only 4B aligned!)
    float* fw   = out + 1 + E;   // E floats (only 4B aligned!)

    // Can the persistent kernel's GRID blocks be fully co-resident?
    bool use_persist = (E == E_EDGES && Nn == N_NODES);
    if (use_persist) {
        int dev = 0, sms = 0, occ = 0;
        cudaGetDevice(&dev);
        cudaDeviceGetAttribute(&sms, cudaDevAttrMultiProcessorCount, dev);
        cudaOccupancyMaxActiveBlocksPerMultiprocessor(&occ, k_persist, TPB, 0);
        if ((long long)occ * sms < GRID) use_persist = false;
    }

    if (use_persist) {
        k_persist<<<GRID, TPB>>>(src, dst, demands, out);
        return;
    }

    // Fallback: proven multi-kernel path.
    const int T   = 256;
    const int BE  = (E + T - 1) / T;
    const int BE2 = (E / 2 + T) / T;
    const int BN  = (N_NODES + T - 1) / T;

    k_zero<<<BN, T>>>(out);
    k_count<<<BE, T>>>(src, E);
    k_init<<<BE, T>>>(src, flow, fw, E);
    for (int it = 0; it < FLOW_ITERS; ++it) {
        int buf = it & 1;
        k_scatter<<<BE2, T>>>(dst, flow, E, buf);
        k_apply<<<BE2, T>>>(src, fw, demands, flow, E, buf);
    }
    k_cost<<<1024, 256>>>(flow, out, E);
}